// round 10
// baseline (speedup 1.0000x reference)
#include <cuda_runtime.h>
#include <cuda_bf16.h>
#include <cstdint>

// ---------------- dims ----------------
#define T_LEN  1024
#define NBG    16       // batch groups (16 batch each) = clusters
#define NGG    8        // gate-slice CTAs per group = cluster size
#define BB     16
#define NTHR   512

// ---------------- lstm smem layout (bytes) ----------------
#define W_OFF   0
#define WPLSZ   65536                  // per-plane W_hh frags: [rg4][ks16][pair2][512B]
#define HB_OFF  131072                 // h double buffer: [buf2][plane2][ks16][512B]
#define HBSZ    16384
#define SP_OFF  163840                 // spill: [kq4][b16][138 floats]
#define SMEM_TOTAL 199168

// xg_kernel smem: W half 128KB + x frags 64KB
#define XG_SMEM 196608

// ---------------- static scratch ----------------
__device__ char          g_XF[(size_t)T_LEN * NBG * 4096];        // x A-frags {hi 2K|lo 2K}
__device__ char          g_WF[262144];                            // W_ih B-frags
__device__ float         g_xg[(size_t)T_LEN * NBG * NGG * 2048];  // xg: [slice][g4][b16][hc32]
__device__ float         g_Hf[256][256];

// ---------------- helpers ----------------
__device__ __forceinline__ uint32_t smem_u32(const void* p) {
  uint32_t a;
  asm("{ .reg .u64 t; cvta.to.shared.u64 t, %1; cvt.u32.u64 %0, t; }" : "=r"(a) : "l"(p));
  return a;
}
__device__ __forceinline__ uint32_t mapa_rank(uint32_t addr, uint32_t rank) {
  uint32_t r;
  asm("mapa.shared::cluster.u32 %0, %1, %2;" : "=r"(r) : "r"(addr), "r"(rank));
  return r;
}
__device__ __forceinline__ void st_cluster_b32(uint32_t addr, uint32_t v) {
  asm volatile("st.shared::cluster.b32 [%0], %1;" :: "r"(addr), "r"(v) : "memory");
}
#define CLUSTER_ARRIVE() asm volatile("barrier.cluster.arrive.aligned;" ::: "memory")
#define CLUSTER_WAIT()   asm volatile("barrier.cluster.wait.aligned;" ::: "memory")

__device__ __forceinline__ float fsig(float x) {
  x = fminf(fmaxf(x, -15.0f), 15.0f);
  return __fdividef(1.0f, 1.0f + __expf(-x));
}
__device__ __forceinline__ float ftanh(float x) {
  x = fminf(fmaxf(x, -15.0f), 15.0f);
  float e = __expf(-2.0f * x);
  return __fdividef(1.0f - e, 1.0f + e);
}
__device__ __forceinline__ void mma16816(float* d, const uint4& a,
                                         uint32_t b0, uint32_t b1) {
  asm volatile(
      "mma.sync.aligned.m16n8k16.row.col.f32.bf16.bf16.f32 "
      "{%0,%1,%2,%3}, {%4,%5,%6,%7}, {%8,%9}, {%0,%1,%2,%3};"
      : "+f"(d[0]), "+f"(d[1]), "+f"(d[2]), "+f"(d[3])
      : "r"(a.x), "r"(a.y), "r"(a.z), "r"(a.w), "r"(b0), "r"(b1));
}
// A-frag offset (batch b, k_in) within one kstep's 512B frag
__device__ __forceinline__ int hx_frag_off(int b, int k_in) {
  int u    = (k_in & 7) >> 1;
  int half = k_in & 1;
  int reg  = ((b >> 3) & 1) + ((k_in >> 3) & 1) * 2;
  return ((b & 7) * 4 + u) * 16 + reg * 4 + half * 2;
}
// B-frag byte offset within its 512B block for (row-in-16 r16, k_in)
__device__ __forceinline__ int b_frag_off(int r16, int k_in) {
  return (((r16 & 7) * 4 + ((k_in & 7) >> 1)) << 4) + ((r16 >> 3) & 1) * 8 +
         ((k_in >> 3) & 1) * 4 + (k_in & 1) * 2;
}

// ---------------- prep kernels ----------------
// x -> A-frags (hi/lo) per (t,bg): [plane 2048][ks4][512B]
__global__ void xf_kernel(const float* __restrict__ x) {
  int id  = blockIdx.x * 256 + threadIdx.x;      // 16,777,216
  int i   = id & 63;
  int t   = (id >> 6) & 1023;
  int bgl = id >> 16;
  float v = x[(size_t)bgl * (T_LEN * 64) + t * 64 + i];
  __nv_bfloat16 hi = __float2bfloat16(v);
  __nv_bfloat16 lo = __float2bfloat16(v - __bfloat162float(hi));
  int off = (i >> 4) * 512 + hx_frag_off(bgl & 15, i & 15);
  char* base = g_XF + ((size_t)t * NBG + (bgl >> 4)) * 4096;
  *(__nv_bfloat16*)(base + off)        = hi;
  *(__nv_bfloat16*)(base + 2048 + off) = lo;
}
// W_ih -> B-frags: [half2][plane2][rg4][ks4][pair8][512B]
__global__ void wf_kernel(const float* __restrict__ W_ih) {
  int id = blockIdx.x * 256 + threadIdx.x;   // 65536
  int gr = id >> 6, k = id & 63;
  float v = W_ih[gr * 64 + k];
  __nv_bfloat16 hi = __float2bfloat16(v);
  __nv_bfloat16 lo = __float2bfloat16(v - __bfloat162float(hi));
  int half = gr >> 9, r = gr & 511;
  int rg = r >> 7, tl = (r >> 3) & 15, pair = tl >> 1;
  int addr = half * 131072 + rg * 16384 + (k >> 4) * 4096 + pair * 512 +
             b_frag_off(r & 15, k & 15);
  *(__nv_bfloat16*)(g_WF + addr)         = hi;
  *(__nv_bfloat16*)(g_WF + 65536 + addr) = lo;
}

// ---------------- xg GEMM: xg = x @ W_ih^T (split-bf16 3 products) ----------------
__global__ void __launch_bounds__(512, 1) xg_kernel() {
  extern __shared__ char smem[];
  char* WS = smem;              // 131072
  char* XS = smem + 131072;     // 65536: [tt16][plane 2048][ks 512]
  const int tid = threadIdx.x;
  const int half = blockIdx.x & 1;
  const int bg   = (blockIdx.x >> 1) & 15;
  const int tc   = blockIdx.x >> 5;

  for (int q = tid; q < 8192; q += 512)
    *(uint4*)(WS + q * 16) = *(const uint4*)(g_WF + (size_t)half * 131072 + q * 16);
  for (int q = tid; q < 4096; q += 512) {
    int tt = q >> 8, inner = q & 255;
    *(uint4*)(XS + q * 16) =
        *(const uint4*)(g_XF + ((size_t)(tc * 16 + tt) * NBG + bg) * 4096 + inner * 16);
  }
  __syncthreads();

  const int wz = tid >> 5, lane = tid & 31;
  const int rg = wz & 3, tq = wz >> 2;

  for (int it = 0; it < 4; it++) {
    int tl_t = it * 4 + tq;
    int t_abs = tc * 16 + tl_t;
    const char* pA = XS + tl_t * 4096;
    float acc[64];
#pragma unroll
    for (int i = 0; i < 64; i++) acc[i] = 0.f;
#pragma unroll
    for (int ks = 0; ks < 4; ks++) {
      uint4 aH = *(const uint4*)(pA + ks * 512 + lane * 16);
      uint4 aL = *(const uint4*)(pA + 2048 + ks * 512 + lane * 16);
#pragma unroll
      for (int p = 0; p < 8; p++) {
        const char* bb = WS + rg * 16384 + ks * 4096 + p * 512 + lane * 16;
        uint4 bH = *(const uint4*)bb;
        uint4 bL = *(const uint4*)(bb + 65536);
        float* a0 = acc + (2 * p) * 4;
        float* a1 = acc + (2 * p + 1) * 4;
        mma16816(a0, aH, bH.x, bH.y);
        mma16816(a0, aH, bL.x, bL.y);
        mma16816(a0, aL, bH.x, bH.y);
        mma16816(a1, aH, bH.z, bH.w);
        mma16816(a1, aH, bL.z, bL.w);
        mma16816(a1, aL, bH.z, bH.w);
      }
    }
    int m = lane >> 2;
#pragma unroll
    for (int tl = 0; tl < 16; tl++) {
      int gr = half * 512 + rg * 128 + tl * 8 + (lane & 3) * 2;
      int g = gr >> 8, gg = (gr >> 5) & 7, hc = gr & 31;
      size_t slice = ((size_t)t_abs * NBG + bg) * 8 + gg;
      float* dst = g_xg + slice * 2048 + g * 512;
      *(float2*)(dst + m * 32 + hc)       = make_float2(acc[tl * 4], acc[tl * 4 + 1]);
      *(float2*)(dst + (m + 8) * 32 + hc) = make_float2(acc[tl * 4 + 2], acc[tl * 4 + 3]);
    }
  }
}

// ---------------- main persistent cluster kernel ----------------
__global__ void __launch_bounds__(NTHR, 1) __cluster_dims__(NGG, 1, 1)
lstm_kernel(const float* __restrict__ W_hh,
            const float* __restrict__ b_ih, const float* __restrict__ b_hh) {
  extern __shared__ char smem[];
  const uint32_t sb = smem_u32(smem);
  const int tid  = threadIdx.x;
  const int wz   = tid >> 5;
  const int lane = tid & 31;
  const int bg   = blockIdx.x >> 3;
  const int gg   = blockIdx.x & 7;
  const int c0   = gg * 32;

  // ---- one-time: W_hh slice -> frags: [plane][rg4][ks16][pair2][512B] ----
  for (int idx = tid; idx < 128 * 256; idx += NTHR) {
    int r = idx >> 8, k = idx & 255;
    int gr = (r >> 5) * 256 + c0 + (r & 31);
    float v = W_hh[gr * 256 + k];
    __nv_bfloat16 hi = __float2bfloat16(v);
    __nv_bfloat16 lo = __float2bfloat16(v - __bfloat162float(hi));
    int rg = r >> 5, pair = (r >> 4) & 1;
    int addr = rg * 16384 + (k >> 4) * 1024 + pair * 512 + b_frag_off(r & 15, k & 15);
    *(__nv_bfloat16*)(smem + W_OFF + addr)         = hi;
    *(__nv_bfloat16*)(smem + W_OFF + WPLSZ + addr) = lo;
  }
  // zero h buffer 0 (h(0) = 0)
#pragma unroll
  for (int i = 0; i < 2; i++)
    *(uint4*)(smem + HB_OFF + (tid + i * NTHR) * 16) = make_uint4(0, 0, 0, 0);

  // MMA mapping: rg = row group (32 rows = 1 gate), kq = k-quarter
  const int rg = wz & 3;
  const int kq = wz >> 2;

  // epilogue mapping: one (b, hc) per thread
  const int eb  = tid >> 5;
  const int ehc = tid & 31;
  float bias[4];
#pragma unroll
  for (int g = 0; g < 4; g++)
    bias[g] = b_ih[g * 256 + c0 + ehc] + b_hh[g * 256 + c0 + ehc];
  float cs = 0.f;

  // DSMEM publish setup: packed-pair offset + 4 mapped target bases
  const int off4 = (gg * 2 + (ehc >> 4)) * 512 +
                   (((eb & 7) * 4 + ((ehc & 7) >> 1)) << 4) +
                   (((eb >> 3) & 1) + ((ehc >> 3) & 1) * 2) * 4;
  uint32_t mbase[4];
#pragma unroll
  for (int i = 0; i < 4; i++)
    mbase[i] = mapa_rank(sb + HB_OFF, (uint32_t)((ehc & 1) * 4 + i));

  const float* xgbase = g_xg + (size_t)(bg * 8 + gg) * 2048 + eb * 32 + ehc;

  __syncthreads();
  CLUSTER_ARRIVE();
  CLUSTER_WAIT();

  // prologue xg(0)
  float xgv[4];
#pragma unroll
  for (int g = 0; g < 4; g++) xgv[g] = __ldcg(xgbase + g * 512);

  for (int t = 0; t < T_LEN; t++) {
    const int tb = t & 1;

    // ---- MMA: 4 ksteps x 4 tiles x 3 products, h from local smem buf ----
    float acc[16];
#pragma unroll
    for (int i = 0; i < 16; i++) acc[i] = 0.f;
#pragma unroll
    for (int j = 0; j < 4; j++) {
      int ks = kq * 4 + j;
      const char* ab = smem + HB_OFF + tb * HBSZ + ks * 512 + lane * 16;
      uint4 aH = *(const uint4*)ab;
      uint4 aL = *(const uint4*)(ab + 8192);
      const char* bb = smem + W_OFF + rg * 16384 + ks * 1024 + lane * 16;
      uint4 bH0 = *(const uint4*)bb;
      uint4 bH1 = *(const uint4*)(bb + 512);
      uint4 bL0 = *(const uint4*)(bb + WPLSZ);
      uint4 bL1 = *(const uint4*)(bb + WPLSZ + 512);
      mma16816(acc + 0,  aH, bH0.x, bH0.y);
      mma16816(acc + 0,  aH, bL0.x, bL0.y);
      mma16816(acc + 0,  aL, bH0.x, bH0.y);
      mma16816(acc + 4,  aH, bH0.z, bH0.w);
      mma16816(acc + 4,  aH, bL0.z, bL0.w);
      mma16816(acc + 4,  aL, bH0.z, bH0.w);
      mma16816(acc + 8,  aH, bH1.x, bH1.y);
      mma16816(acc + 8,  aH, bL1.x, bL1.y);
      mma16816(acc + 8,  aL, bH1.x, bH1.y);
      mma16816(acc + 12, aH, bH1.z, bH1.w);
      mma16816(acc + 12, aH, bL1.z, bL1.w);
      mma16816(acc + 12, aL, bH1.z, bH1.w);
    }

    // ---- spill partials: [kq][b16][138] ----
    {
      float* sp = (float*)(smem + SP_OFF) + kq * 2208;
      int q = lane >> 2, cp2 = (lane & 3) * 2;
#pragma unroll
      for (int tl = 0; tl < 4; tl++) {
        int r = rg * 32 + tl * 8 + cp2;
        *(float2*)(sp + q * 138 + r)       = make_float2(acc[tl * 4], acc[tl * 4 + 1]);
        *(float2*)(sp + (q + 8) * 138 + r) = make_float2(acc[tl * 4 + 2], acc[tl * 4 + 3]);
      }
    }
    __syncthreads();

    // ---- prefetch xg(t+1) (flies through epilogue + barrier) ----
    float xgn[4];
    {
      int tn = (t + 1 < T_LEN) ? t + 1 : 0;
      const float* xp = xgbase + (size_t)tn * (NBG * 8) * 2048;
#pragma unroll
      for (int g = 0; g < 4; g++) xgn[g] = __ldcg(xp + g * 512);
    }

    // ---- epilogue: sum 4 partials + xg + bias, activations, DSMEM publish ----
    {
      const float* sp = (const float*)(smem + SP_OFF);
      float gsum[4];
#pragma unroll
      for (int g = 0; g < 4; g++) {
        float s = xgv[g] + bias[g];
#pragma unroll
        for (int q = 0; q < 4; q++) s += sp[q * 2208 + eb * 138 + g * 32 + ehc];
        gsum[g] = s;
      }
      float iv = fsig(gsum[0]), fv = fsig(gsum[1]);
      float cv = ftanh(gsum[2]), ov = fsig(gsum[3]);
      float cn = fv * cs + iv * cv;
      cs = cn;
      float hvv = ov * ftanh(cn);
      if (t < T_LEN - 1) {
        __nv_bfloat16 hi = __float2bfloat16(hvv);
        __nv_bfloat16 lo = __float2bfloat16(hvv - __bfloat162float(hi));
        uint32_t hb = (uint32_t)__bfloat16_as_ushort(hi);
        uint32_t lb = (uint32_t)__bfloat16_as_ushort(lo);
        uint32_t nh = __shfl_xor_sync(0xFFFFFFFFu, hb, 1);
        uint32_t nl = __shfl_xor_sync(0xFFFFFFFFu, lb, 1);
        uint32_t packH = (ehc & 1) ? ((hb << 16) | nh) : ((nh << 16) | hb);
        uint32_t packL = (ehc & 1) ? ((lb << 16) | nl) : ((nl << 16) | lb);
        uint32_t doff = (uint32_t)(((t + 1) & 1) * HBSZ + off4);
#pragma unroll
        for (int i = 0; i < 4; i++) {
          st_cluster_b32(mbase[i] + doff, packH);
          st_cluster_b32(mbase[i] + doff + 8192, packL);
        }
      } else {
        g_Hf[bg * BB + eb][c0 + ehc] = hvv;
      }
    }
#pragma unroll
    for (int g = 0; g < 4; g++) xgv[g] = xgn[g];

    // ---- one cluster rendezvous per step (release stores / acquire peers') ----
    CLUSTER_ARRIVE();
    CLUSTER_WAIT();
  }
}

// ---------------- fc ----------------
__global__ void fc_kernel(const float* __restrict__ fc_w,
                          const float* __restrict__ fc_b,
                          float* __restrict__ out) {
  int b = blockIdx.x;
  float s = g_Hf[b][threadIdx.x] * fc_w[threadIdx.x];
#pragma unroll
  for (int o = 16; o; o >>= 1) s += __shfl_xor_sync(0xFFFFFFFFu, s, o);
  __shared__ float ps[8];
  if ((threadIdx.x & 31) == 0) ps[threadIdx.x >> 5] = s;
  __syncthreads();
  if (threadIdx.x == 0) {
    float tt = 0.f;
#pragma unroll
    for (int i = 0; i < 8; i++) tt += ps[i];
    out[b] = tt + fc_b[0];
  }
}

// ---------------- launch ----------------
extern "C" void kernel_launch(void* const* d_in, const int* in_sizes, int n_in,
                              void* d_out, int out_size) {
  const float* x    = (const float*)d_in[0];
  const float* W_ih = (const float*)d_in[1];
  const float* W_hh = (const float*)d_in[2];
  const float* b_ih = (const float*)d_in[3];
  const float* b_hh = (const float*)d_in[4];
  const float* fc_w = (const float*)d_in[5];
  const float* fc_b = (const float*)d_in[6];
  float* out = (float*)d_out;

  static bool init = false;
  if (!init) {
    cudaFuncSetAttribute(lstm_kernel,
                         cudaFuncAttributeMaxDynamicSharedMemorySize, SMEM_TOTAL);
    cudaFuncSetAttribute(xg_kernel,
                         cudaFuncAttributeMaxDynamicSharedMemorySize, XG_SMEM);
    init = true;
  }

  xf_kernel<<<65536, 256>>>(x);
  wf_kernel<<<256, 256>>>(W_ih);
  xg_kernel<<<2048, 512, XG_SMEM>>>();
  lstm_kernel<<<NBG * NGG, NTHR, SMEM_TOTAL>>>(W_hh, b_ih, b_hh);
  fc_kernel<<<256, 256>>>(fc_w, fc_b, out);
}

// round 11
// speedup vs baseline: 2.2578x; 2.2578x over previous
#include <cuda_runtime.h>
#include <cuda_bf16.h>
#include <cstdint>

// ---------------- dims ----------------
#define T_LEN  1024
#define NBG    16       // batch groups (16 batch each)
#define NGG    8        // gate-slice CTAs per group
#define BB     16
#define NTHR   256

// ---------------- lstm smem layout (bytes) ----------------
#define W_OFF   0
#define WPLSZ   65536                  // per-plane W_hh frags: [rg4][ks16][pair2][512B]
#define HX_OFF  131072                 // h frags: [plane2][ks16][512B] = 16KB
#define SP_OFF  147456                 // spill: [kh2][b16][138 floats]
#define SP_HALF 8832
#define SMEM_TOTAL (SP_OFF + 2 * SP_HALF)   // 165120

// xg_kernel smem: W half 128KB + x frags 64KB
#define XG_SMEM 196608

// ---------------- static scratch ----------------
__device__ char          g_B[(size_t)(T_LEN + 1) * NBG * 16384];  // h ring {hi 8K|lo 8K}
__device__ char          g_XF[(size_t)T_LEN * NBG * 4096];        // x A-frags {hi 2K|lo 2K}
__device__ char          g_WF[262144];                            // W_ih B-frags
__device__ float         g_xg[(size_t)T_LEN * NBG * NGG * 2048];  // xg: [slice][g4][b16][hc32]
__device__ float         g_Hf[256][256];
__device__ unsigned int  g_cnt[NBG * 32];

// ---------------- helpers ----------------
__device__ __forceinline__ unsigned int ld_acq(const unsigned int* p) {
  unsigned int v;
  asm volatile("ld.acquire.gpu.global.u32 %0, [%1];" : "=r"(v) : "l"(p) : "memory");
  return v;
}
__device__ __forceinline__ void red_rel(unsigned int* p) {
  asm volatile("red.release.gpu.global.add.u32 [%0], 1;" :: "l"(p) : "memory");
}
__device__ __forceinline__ float fsig(float x) {
  x = fminf(fmaxf(x, -15.0f), 15.0f);
  return __fdividef(1.0f, 1.0f + __expf(-x));
}
__device__ __forceinline__ float ftanh(float x) {
  x = fminf(fmaxf(x, -15.0f), 15.0f);
  float e = __expf(-2.0f * x);
  return __fdividef(1.0f - e, 1.0f + e);
}
__device__ __forceinline__ void mma16816(float* d, const uint4& a,
                                         uint32_t b0, uint32_t b1) {
  asm volatile(
      "mma.sync.aligned.m16n8k16.row.col.f32.bf16.bf16.f32 "
      "{%0,%1,%2,%3}, {%4,%5,%6,%7}, {%8,%9}, {%0,%1,%2,%3};"
      : "+f"(d[0]), "+f"(d[1]), "+f"(d[2]), "+f"(d[3])
      : "r"(a.x), "r"(a.y), "r"(a.z), "r"(a.w), "r"(b0), "r"(b1));
}
// A-frag offset (batch b, k_in) within one kstep's 512B frag
__device__ __forceinline__ int hx_frag_off(int b, int k_in) {
  int u    = (k_in & 7) >> 1;
  int half = k_in & 1;
  int reg  = ((b >> 3) & 1) + ((k_in >> 3) & 1) * 2;
  return ((b & 7) * 4 + u) * 16 + reg * 4 + half * 2;
}
// B-frag byte offset within its 512B block for (row-in-16 r16, k_in)
__device__ __forceinline__ int b_frag_off(int r16, int k_in) {
  return (((r16 & 7) * 4 + ((k_in & 7) >> 1)) << 4) + ((r16 >> 3) & 1) * 8 +
         ((k_in >> 3) & 1) * 4 + (k_in & 1) * 2;
}

// ---------------- prep kernels ----------------
__global__ void reset_kernel() {
  if (threadIdx.x < NBG * 32) g_cnt[threadIdx.x] = 0u;
}
__global__ void zring_kernel() {   // zero h ring slot 0 (16KB x 16 groups)
  int id = blockIdx.x * 256 + threadIdx.x;   // 16384
  *(uint4*)(g_B + (size_t)(id >> 10) * 16384 + (id & 1023) * 16) =
      make_uint4(0, 0, 0, 0);
}
// x -> A-frags (hi/lo) per (t,bg): [plane 2048][ks4][512B]
__global__ void xf_kernel(const float* __restrict__ x) {
  int id  = blockIdx.x * 256 + threadIdx.x;      // 16,777,216
  int i   = id & 63;
  int t   = (id >> 6) & 1023;
  int bgl = id >> 16;
  float v = x[(size_t)bgl * (T_LEN * 64) + t * 64 + i];
  __nv_bfloat16 hi = __float2bfloat16(v);
  __nv_bfloat16 lo = __float2bfloat16(v - __bfloat162float(hi));
  int off = (i >> 4) * 512 + hx_frag_off(bgl & 15, i & 15);
  char* base = g_XF + ((size_t)t * NBG + (bgl >> 4)) * 4096;
  *(__nv_bfloat16*)(base + off)        = hi;
  *(__nv_bfloat16*)(base + 2048 + off) = lo;
}
// W_ih -> B-frags: [half2][plane2][rg4][ks4][pair8][512B]
__global__ void wf_kernel(const float* __restrict__ W_ih) {
  int id = blockIdx.x * 256 + threadIdx.x;   // 65536
  int gr = id >> 6, k = id & 63;
  float v = W_ih[gr * 64 + k];
  __nv_bfloat16 hi = __float2bfloat16(v);
  __nv_bfloat16 lo = __float2bfloat16(v - __bfloat162float(hi));
  int half = gr >> 9, r = gr & 511;
  int rg = r >> 7, pair = ((r >> 3) & 15) >> 1;
  int addr = half * 131072 + rg * 16384 + (k >> 4) * 4096 + pair * 512 +
             b_frag_off(r & 15, k & 15);
  *(__nv_bfloat16*)(g_WF + addr)         = hi;
  *(__nv_bfloat16*)(g_WF + 65536 + addr) = lo;
}

// ---------------- xg GEMM: xg = x @ W_ih^T (split-bf16 3 products) ----------------
__global__ void __launch_bounds__(512, 1) xg_kernel() {
  extern __shared__ char smem[];
  char* WS = smem;              // 131072
  char* XS = smem + 131072;     // 65536: [tt16][plane 2048][ks 512]
  const int tid = threadIdx.x;
  const int half = blockIdx.x & 1;
  const int bg   = (blockIdx.x >> 1) & 15;
  const int tc   = blockIdx.x >> 5;

  for (int q = tid; q < 8192; q += 512)
    *(uint4*)(WS + q * 16) = *(const uint4*)(g_WF + (size_t)half * 131072 + q * 16);
  for (int q = tid; q < 4096; q += 512) {
    int tt = q >> 8, inner = q & 255;
    *(uint4*)(XS + q * 16) =
        *(const uint4*)(g_XF + ((size_t)(tc * 16 + tt) * NBG + bg) * 4096 + inner * 16);
  }
  __syncthreads();

  const int wz = tid >> 5, lane = tid & 31;
  const int rg = wz & 3, tq = wz >> 2;

  for (int it = 0; it < 4; it++) {
    int tl_t = it * 4 + tq;
    int t_abs = tc * 16 + tl_t;
    const char* pA = XS + tl_t * 4096;
    float acc[64];
#pragma unroll
    for (int i = 0; i < 64; i++) acc[i] = 0.f;
#pragma unroll
    for (int ks = 0; ks < 4; ks++) {
      uint4 aH = *(const uint4*)(pA + ks * 512 + lane * 16);
      uint4 aL = *(const uint4*)(pA + 2048 + ks * 512 + lane * 16);
#pragma unroll
      for (int p = 0; p < 8; p++) {
        const char* bb = WS + rg * 16384 + ks * 4096 + p * 512 + lane * 16;
        uint4 bH = *(const uint4*)bb;
        uint4 bL = *(const uint4*)(bb + 65536);
        float* a0 = acc + (2 * p) * 4;
        float* a1 = acc + (2 * p + 1) * 4;
        mma16816(a0, aH, bH.x, bH.y);
        mma16816(a0, aH, bL.x, bL.y);
        mma16816(a0, aL, bH.x, bH.y);
        mma16816(a1, aH, bH.z, bH.w);
        mma16816(a1, aH, bL.z, bL.w);
        mma16816(a1, aL, bH.z, bH.w);
      }
    }
    int m = lane >> 2;
#pragma unroll
    for (int tl = 0; tl < 16; tl++) {
      int gr = half * 512 + rg * 128 + tl * 8 + (lane & 3) * 2;
      int g = gr >> 8, gg = (gr >> 5) & 7, hc = gr & 31;
      size_t slice = ((size_t)t_abs * NBG + bg) * 8 + gg;
      float* dst = g_xg + slice * 2048 + g * 512;
      *(float2*)(dst + m * 32 + hc)       = make_float2(acc[tl * 4], acc[tl * 4 + 1]);
      *(float2*)(dst + (m + 8) * 32 + hc) = make_float2(acc[tl * 4 + 2], acc[tl * 4 + 3]);
    }
  }
}

// ---------------- main persistent kernel ----------------
__global__ void __launch_bounds__(NTHR, 1) lstm_kernel(
    const float* __restrict__ W_hh,
    const float* __restrict__ b_ih, const float* __restrict__ b_hh) {
  extern __shared__ char smem[];
  const int tid  = threadIdx.x;
  const int wz   = tid >> 5;
  const int lane = tid & 31;
  const int bg   = blockIdx.x >> 3;
  const int gg   = blockIdx.x & 7;
  const int c0   = gg * 32;

  // ---- one-time: W_hh slice -> frags: [plane][rg4][ks16][pair2][512B] ----
  for (int idx = tid; idx < 128 * 256; idx += NTHR) {
    int r = idx >> 8, k = idx & 255;
    int gr = (r >> 5) * 256 + c0 + (r & 31);
    float v = W_hh[gr * 256 + k];
    __nv_bfloat16 hi = __float2bfloat16(v);
    __nv_bfloat16 lo = __float2bfloat16(v - __bfloat162float(hi));
    int rg = r >> 5, pair = (r >> 4) & 1;
    int addr = rg * 16384 + (k >> 4) * 1024 + pair * 512 + b_frag_off(r & 15, k & 15);
    *(__nv_bfloat16*)(smem + W_OFF + addr)         = hi;
    *(__nv_bfloat16*)(smem + W_OFF + WPLSZ + addr) = lo;
  }

  // h copy-in: 4 x 16B chunks per thread (16KB, both planes)
  int hoff[4];
#pragma unroll
  for (int i = 0; i < 4; i++) {
    int q = tid + i * NTHR;
    hoff[i] = (q >> 9) * 8192 + (q & 511) * 16;
  }

  // MMA mapping: rg = row group (32 rows = 1 gate), kh = k-half (8 ksteps)
  const int rg = wz & 3;
  const int kh = wz >> 2;

  // epilogue mapping: (eb, ehc) and (eb+8, ehc)
  const int eb  = tid >> 5;
  const int ehc = tid & 31;
  const int eks = gg * 2 + (ehc >> 4);
  const int ekin = ehc & 15;
  float bias[4];
#pragma unroll
  for (int g = 0; g < 4; g++)
    bias[g] = b_ih[g * 256 + c0 + ehc] + b_hh[g * 256 + c0 + ehc];
  float cs[2] = {0.f, 0.f};

  unsigned int* flag = &g_cnt[bg * 32];
  const float* xgbase = g_xg + (size_t)(bg * 8 + gg) * 2048 + eb * 32 + ehc;
  __syncthreads();

  for (int t = 0; t < T_LEN; t++) {
    const char* ringT  = g_B + ((size_t)t * NBG + bg) * 16384;
    char*       ringT1 = g_B + ((size_t)(t + 1) * NBG + bg) * 16384;

    // ---- prefetch xg(t) (h-independent), then wait for h(t) ----
    float xgv[2][4];
    {
      const float* xp = xgbase + (size_t)t * (NBG * NGG) * 2048;
#pragma unroll
      for (int uu = 0; uu < 2; uu++)
#pragma unroll
        for (int g = 0; g < 4; g++)
          xgv[uu][g] = __ldcg(xp + g * 512 + uu * 256);
    }
    if (t) {
      unsigned int target = (unsigned int)(NGG * t);
      while (ld_acq(flag) < target) { }
    }
    uint4 hv[4];
#pragma unroll
    for (int i = 0; i < 4; i++) hv[i] = __ldcg((const uint4*)(ringT + hoff[i]));
#pragma unroll
    for (int i = 0; i < 4; i++) *(uint4*)(smem + HX_OFF + hoff[i]) = hv[i];
    __syncthreads();

    // ---- MMA: 8 ksteps x 4 tiles x 3 products per warp ----
    float acc[16];
#pragma unroll
    for (int i = 0; i < 16; i++) acc[i] = 0.f;
#pragma unroll
    for (int j = 0; j < 8; j++) {
      int ks = kh * 8 + j;
      const char* ab = smem + HX_OFF + ks * 512 + lane * 16;
      uint4 aH = *(const uint4*)ab;
      uint4 aL = *(const uint4*)(ab + 8192);
      const char* bb = smem + W_OFF + rg * 16384 + ks * 1024 + lane * 16;
      uint4 bH0 = *(const uint4*)bb;
      uint4 bH1 = *(const uint4*)(bb + 512);
      uint4 bL0 = *(const uint4*)(bb + WPLSZ);
      uint4 bL1 = *(const uint4*)(bb + WPLSZ + 512);
      mma16816(acc + 0,  aH, bH0.x, bH0.y);
      mma16816(acc + 0,  aH, bL0.x, bL0.y);
      mma16816(acc + 0,  aL, bH0.x, bH0.y);
      mma16816(acc + 4,  aH, bH0.z, bH0.w);
      mma16816(acc + 4,  aH, bL0.z, bL0.w);
      mma16816(acc + 4,  aL, bH0.z, bH0.w);
      mma16816(acc + 8,  aH, bH1.x, bH1.y);
      mma16816(acc + 8,  aH, bL1.x, bL1.y);
      mma16816(acc + 8,  aL, bH1.x, bH1.y);
      mma16816(acc + 12, aH, bH1.z, bH1.w);
      mma16816(acc + 12, aH, bL1.z, bL1.w);
      mma16816(acc + 12, aL, bH1.z, bH1.w);
    }

    // ---- spill partials: [kh][b16][138] ----
    {
      float* sp = (float*)(smem + SP_OFF) + kh * 2208;
      int q = lane >> 2, cp2 = (lane & 3) * 2;
#pragma unroll
      for (int tl = 0; tl < 4; tl++) {
        int r = rg * 32 + tl * 8 + cp2;
        *(float2*)(sp + q * 138 + r)       = make_float2(acc[tl * 4], acc[tl * 4 + 1]);
        *(float2*)(sp + (q + 8) * 138 + r) = make_float2(acc[tl * 4 + 2], acc[tl * 4 + 3]);
      }
    }
    __syncthreads();

    // ---- epilogue: combine halves + xg + bias, activations, publish h(t+1) ----
    {
      const float* s0 = (const float*)(smem + SP_OFF);
      const float* s1 = s0 + 2208;
#pragma unroll
      for (int uu = 0; uu < 2; uu++) {
        int b = eb + uu * 8;
        float gsum[4];
#pragma unroll
        for (int g = 0; g < 4; g++)
          gsum[g] = xgv[uu][g] + bias[g] +
                    s0[b * 138 + g * 32 + ehc] + s1[b * 138 + g * 32 + ehc];
        float iv = fsig(gsum[0]), fv = fsig(gsum[1]);
        float cv = ftanh(gsum[2]), ov = fsig(gsum[3]);
        float cn = fv * cs[uu] + iv * cv;
        cs[uu] = cn;
        float hvv = ov * ftanh(cn);
        __nv_bfloat16 hi = __float2bfloat16(hvv);
        __nv_bfloat16 lo = __float2bfloat16(hvv - __bfloat162float(hi));
        int off = eks * 512 + hx_frag_off(b, ekin);
        *(__nv_bfloat16*)(ringT1 + off)        = hi;
        *(__nv_bfloat16*)(ringT1 + 8192 + off) = lo;
        if (t == T_LEN - 1) g_Hf[bg * BB + b][c0 + ehc] = hvv;
      }
    }
    __syncthreads();
    if (tid == 0) red_rel(flag);
  }
}

// ---------------- fc ----------------
__global__ void fc_kernel(const float* __restrict__ fc_w,
                          const float* __restrict__ fc_b,
                          float* __restrict__ out) {
  int b = blockIdx.x;
  float s = g_Hf[b][threadIdx.x] * fc_w[threadIdx.x];
#pragma unroll
  for (int o = 16; o; o >>= 1) s += __shfl_xor_sync(0xFFFFFFFFu, s, o);
  __shared__ float ps[8];
  if ((threadIdx.x & 31) == 0) ps[threadIdx.x >> 5] = s;
  __syncthreads();
  if (threadIdx.x == 0) {
    float tt = 0.f;
#pragma unroll
    for (int i = 0; i < 8; i++) tt += ps[i];
    out[b] = tt + fc_b[0];
  }
}

// ---------------- launch ----------------
extern "C" void kernel_launch(void* const* d_in, const int* in_sizes, int n_in,
                              void* d_out, int out_size) {
  const float* x    = (const float*)d_in[0];
  const float* W_ih = (const float*)d_in[1];
  const float* W_hh = (const float*)d_in[2];
  const float* b_ih = (const float*)d_in[3];
  const float* b_hh = (const float*)d_in[4];
  const float* fc_w = (const float*)d_in[5];
  const float* fc_b = (const float*)d_in[6];
  float* out = (float*)d_out;

  static bool init = false;
  if (!init) {
    cudaFuncSetAttribute(lstm_kernel,
                         cudaFuncAttributeMaxDynamicSharedMemorySize, SMEM_TOTAL);
    cudaFuncSetAttribute(xg_kernel,
                         cudaFuncAttributeMaxDynamicSharedMemorySize, XG_SMEM);
    init = true;
  }

  reset_kernel<<<1, 512>>>();
  zring_kernel<<<64, 256>>>();
  xf_kernel<<<65536, 256>>>(x);
  wf_kernel<<<256, 256>>>(W_ih);
  xg_kernel<<<2048, 512, XG_SMEM>>>();
  lstm_kernel<<<NBG * NGG, NTHR, SMEM_TOTAL>>>(W_hh, b_ih, b_hh);
  fc_kernel<<<256, 256>>>(fc_w, fc_b, out);
}